// round 1
// baseline (speedup 1.0000x reference)
#include <cuda_runtime.h>
#include <cuda_bf16.h>
#include <cstdint>

// Shapes
#define B_   128
#define L_   1024
#define RNN_ 1024
#define ATT_ 512
#define KSPLIT 8   // k-split for K1
#define LSPLIT 8   // l-split for K2/K4 (128 l per chunk)

// Scratch (device globals — allocation-free)
__device__ __align__(16) float g_atth_part[KSPLIT][B_ * ATT_];   // 2 MB
__device__ __align__(16) float g_dot[B_ * L_];                   // 512 KB
__device__ __align__(16) float g_weight[B_ * L_];                // 512 KB
__device__ __align__(16) float g_part[LSPLIT][B_ * RNN_];        // 4 MB

__device__ __forceinline__ float tanh_fast(float x) {
    float y;
    asm("tanh.approx.f32 %0, %1;" : "=f"(y) : "f"(x));
    return y;
}

// ------------------------------------------------------------------
// K1: att_h partials = h[128,1024] @ W[512,1024]^T, 64x64 tiles, ksplit=8
// grid (8 a-tiles, 2 b-tiles, 8 k-splits), 256 threads (16x16, 4x4 micro)
// ------------------------------------------------------------------
__global__ void k1_gemm(const float* __restrict__ h, const float* __restrict__ W) {
    __shared__ float Hs[64][17];
    __shared__ float Ws[64][17];
    const int a0 = blockIdx.x * 64;
    const int b0 = blockIdx.y * 64;
    const int k0 = blockIdx.z * (RNN_ / KSPLIT);  // 128-wide k range
    const int tid = threadIdx.x;
    const int tx = tid & 15;
    const int ty = tid >> 4;
    const int lr = tid >> 2;         // 0..63
    const int lc = (tid & 3) * 4;    // 0,4,8,12

    float c[4][4];
#pragma unroll
    for (int i = 0; i < 4; i++)
#pragma unroll
        for (int j = 0; j < 4; j++) c[i][j] = 0.f;

    for (int kk = 0; kk < RNN_ / KSPLIT; kk += 16) {
        float4 hv = *(const float4*)(h + (size_t)(b0 + lr) * RNN_ + k0 + kk + lc);
        float4 wv = *(const float4*)(W + (size_t)(a0 + lr) * RNN_ + k0 + kk + lc);
        Hs[lr][lc] = hv.x; Hs[lr][lc + 1] = hv.y; Hs[lr][lc + 2] = hv.z; Hs[lr][lc + 3] = hv.w;
        Ws[lr][lc] = wv.x; Ws[lr][lc + 1] = wv.y; Ws[lr][lc + 2] = wv.z; Ws[lr][lc + 3] = wv.w;
        __syncthreads();
#pragma unroll
        for (int k = 0; k < 16; k++) {
            float hr[4], wr[4];
#pragma unroll
            for (int i = 0; i < 4; i++) hr[i] = Hs[ty * 4 + i][k];
#pragma unroll
            for (int j = 0; j < 4; j++) wr[j] = Ws[tx * 4 + j][k];
#pragma unroll
            for (int i = 0; i < 4; i++)
#pragma unroll
                for (int j = 0; j < 4; j++) c[i][j] += hr[i] * wr[j];
        }
        __syncthreads();
    }
#pragma unroll
    for (int i = 0; i < 4; i++)
#pragma unroll
        for (int j = 0; j < 4; j++)
            g_atth_part[blockIdx.z][(b0 + ty * 4 + i) * ATT_ + a0 + tx * 4 + j] = c[i][j];
}

// ------------------------------------------------------------------
// K2: dot[b,l] = sum_a tanh(f2[b,l,a] + att_h[b,a]) * w_alpha[a] + b_alpha
// grid (128 b, 8 l-chunks), 256 threads (8 warps x 16 l each)
// att_h & w_alpha live in per-lane REGISTERS (16 floats each) — zero LDS in hot loop.
// ------------------------------------------------------------------
__global__ void k2_dot(const float* __restrict__ f2,
                       const float* __restrict__ w_alpha,
                       const float* __restrict__ b_h2att,
                       const float* __restrict__ b_alpha) {
    __shared__ __align__(16) float atth[ATT_];
    __shared__ __align__(16) float wal[ATT_];
    const int b  = blockIdx.x;
    const int lc = blockIdx.y;
    const int tid = threadIdx.x;

    for (int i = tid; i < ATT_; i += 256) {
        float s = b_h2att[i];
#pragma unroll
        for (int p = 0; p < KSPLIT; p++) s += g_atth_part[p][b * ATT_ + i];
        atth[i] = s;
        wal[i] = w_alpha[i];
    }
    __syncthreads();

    const int warp = tid >> 5;
    const int lane = tid & 31;
    float4 ah[4], wa[4];
#pragma unroll
    for (int j = 0; j < 4; j++) {
        ah[j] = ((const float4*)atth)[lane + 32 * j];
        wa[j] = ((const float4*)wal)[lane + 32 * j];
    }
    const float balpha = *b_alpha;
    const float* base = f2 + ((size_t)b * L_ + (size_t)lc * (L_ / LSPLIT)) * ATT_;

    for (int li = warp; li < L_ / LSPLIT; li += 8) {
        const float4* row = (const float4*)(base + (size_t)li * ATT_);
        float s = 0.f;
#pragma unroll
        for (int j = 0; j < 4; j++) {
            float4 v = row[lane + 32 * j];
            s += tanh_fast(v.x + ah[j].x) * wa[j].x;
            s += tanh_fast(v.y + ah[j].y) * wa[j].y;
            s += tanh_fast(v.z + ah[j].z) * wa[j].z;
            s += tanh_fast(v.w + ah[j].w) * wa[j].w;
        }
#pragma unroll
        for (int o = 16; o; o >>= 1) s += __shfl_xor_sync(0xffffffffu, s, o);
        if (lane == 0) g_dot[b * L_ + lc * (L_ / LSPLIT) + li] = s + balpha;
    }
}

// ------------------------------------------------------------------
// K3: weight[b,l] = exp(dot-max)*mask / sum(exp(dot-max)*mask)
// (inner softmax denominator cancels algebraically)
// grid 128, 256 threads, float4 per thread
// ------------------------------------------------------------------
__global__ void k3_softmax(const float* __restrict__ mask) {
    const int b = blockIdx.x;
    const int tid = threadIdx.x;
    __shared__ float red[8];
    __shared__ float s_stat;

    float4 d = ((const float4*)(g_dot + b * L_))[tid];
    float4 m = ((const float4*)(mask + (size_t)b * L_))[tid];

    float mx = fmaxf(fmaxf(d.x, d.y), fmaxf(d.z, d.w));
#pragma unroll
    for (int o = 16; o; o >>= 1) mx = fmaxf(mx, __shfl_xor_sync(0xffffffffu, mx, o));
    if ((tid & 31) == 0) red[tid >> 5] = mx;
    __syncthreads();
    if (tid < 8) {
        float v = red[tid];
#pragma unroll
        for (int o = 4; o; o >>= 1) v = fmaxf(v, __shfl_xor_sync(0xffu, v, o));
        if (tid == 0) s_stat = v;
    }
    __syncthreads();
    const float bmax = s_stat;

    float4 e;
    e.x = __expf(d.x - bmax) * m.x;
    e.y = __expf(d.y - bmax) * m.y;
    e.z = __expf(d.z - bmax) * m.z;
    e.w = __expf(d.w - bmax) * m.w;
    float s = e.x + e.y + e.z + e.w;
#pragma unroll
    for (int o = 16; o; o >>= 1) s += __shfl_xor_sync(0xffffffffu, s, o);
    if ((tid & 31) == 0) red[tid >> 5] = s;
    __syncthreads();
    if (tid < 8) {
        float v = red[tid];
#pragma unroll
        for (int o = 4; o; o >>= 1) v += __shfl_xor_sync(0xffu, v, o);
        if (tid == 0) s_stat = v;
    }
    __syncthreads();
    const float inv = 1.0f / s_stat;
    float4 w4 = make_float4(e.x * inv, e.y * inv, e.z * inv, e.w * inv);
    ((float4*)(g_weight + b * L_))[tid] = w4;
}

// ------------------------------------------------------------------
// K4: partial[s][b,d] = sum_{l in split s} weight[b,l] * f1[b,l,d]
// grid (128 b, 8 splits) = 1024 blocks, 256 threads, float4 per thread (full 1024-d row)
// ------------------------------------------------------------------
__global__ void k4_weighted(const float* __restrict__ f1) {
    const int b = blockIdx.x;
    const int s = blockIdx.y;
    const int tid = threadIdx.x;
    __shared__ float ws[L_ / LSPLIT];
    if (tid < L_ / LSPLIT) ws[tid] = g_weight[b * L_ + s * (L_ / LSPLIT) + tid];
    __syncthreads();

    const float4* base = (const float4*)(f1 + ((size_t)b * L_ + (size_t)s * (L_ / LSPLIT)) * RNN_) + tid;
    float4 acc = make_float4(0.f, 0.f, 0.f, 0.f);
#pragma unroll 8
    for (int l = 0; l < L_ / LSPLIT; l++) {
        const float w = ws[l];
        float4 v = base[(size_t)l * (RNN_ / 4)];
        acc.x += w * v.x;
        acc.y += w * v.y;
        acc.z += w * v.z;
        acc.w += w * v.w;
    }
    ((float4*)(g_part[s] + b * RNN_))[tid] = acc;
}

// ------------------------------------------------------------------
// K5: out[b,d] = sum_s partial[s][b,d]   (deterministic combine)
// grid 128 blocks x 256 threads, float4 per thread
// ------------------------------------------------------------------
__global__ void k5_combine(float* __restrict__ out) {
    const int i = blockIdx.x * 256 + threadIdx.x;  // float4 index, 32768 total
    float4 a = make_float4(0.f, 0.f, 0.f, 0.f);
#pragma unroll
    for (int s = 0; s < LSPLIT; s++) {
        float4 v = ((const float4*)g_part)[(size_t)s * (B_ * RNN_ / 4) + i];
        a.x += v.x; a.y += v.y; a.z += v.z; a.w += v.w;
    }
    ((float4*)out)[i] = a;
}

extern "C" void kernel_launch(void* const* d_in, const int* in_sizes, int n_in,
                              void* d_out, int out_size) {
    const float* h    = (const float*)d_in[0];
    const float* f1   = (const float*)d_in[1];  // att_feats1 [128,1024,1024]
    const float* f2   = (const float*)d_in[2];  // att_feats2 [128,1024,512]
    const float* mask = (const float*)d_in[3];
    const float* W    = (const float*)d_in[4];  // [512,1024]
    const float* bh   = (const float*)d_in[5];  // [512]
    const float* wal  = (const float*)d_in[6];  // [512]
    const float* bal  = (const float*)d_in[7];  // scalar
    float* out = (float*)d_out;

    k1_gemm<<<dim3(ATT_ / 64, B_ / 64, KSPLIT), 256>>>(h, W);
    k2_dot<<<dim3(B_, LSPLIT), 256>>>(f2, wal, bh, bal);
    k3_softmax<<<B_, 256>>>(mask);
    k4_weighted<<<dim3(B_, LSPLIT), 256>>>(f1);
    k5_combine<<<B_ * RNN_ / 1024, 256>>>(out);
}

// round 2
// speedup vs baseline: 1.4953x; 1.4953x over previous
#include <cuda_runtime.h>
#include <cuda_bf16.h>
#include <cstdint>

// Shapes
#define B_   128
#define L_   1024
#define RNN_ 1024
#define ATT_ 512
#define KSPLIT 8   // k-split for K1
#define LSPLIT 8   // l-split for K2/K4 (128 l per chunk)

// Scratch (device globals — allocation-free)
__device__ __align__(16) float g_atth_part[KSPLIT][B_ * ATT_];   // 2 MB
__device__ __align__(16) float g_dot[B_ * L_];                   // 512 KB
__device__ __align__(16) float g_weight[B_ * L_];                // 512 KB
__device__ __align__(16) float g_part[LSPLIT][B_ * RNN_];        // 4 MB

__device__ __forceinline__ float tanh_fast(float x) {
    float y;
    asm("tanh.approx.f32 %0, %1;" : "=f"(y) : "f"(x));
    return y;
}

// ------------------------------------------------------------------
// K1: att_h partials = h[128,1024] @ W[512,1024]^T, 64x64 tiles, ksplit=8
// ------------------------------------------------------------------
__global__ void k1_gemm(const float* __restrict__ h, const float* __restrict__ W) {
    __shared__ float Hs[64][17];
    __shared__ float Ws[64][17];
    const int a0 = blockIdx.x * 64;
    const int b0 = blockIdx.y * 64;
    const int k0 = blockIdx.z * (RNN_ / KSPLIT);
    const int tid = threadIdx.x;
    const int tx = tid & 15;
    const int ty = tid >> 4;
    const int lr = tid >> 2;
    const int lc = (tid & 3) * 4;

    float c[4][4];
#pragma unroll
    for (int i = 0; i < 4; i++)
#pragma unroll
        for (int j = 0; j < 4; j++) c[i][j] = 0.f;

    for (int kk = 0; kk < RNN_ / KSPLIT; kk += 16) {
        float4 hv = *(const float4*)(h + (size_t)(b0 + lr) * RNN_ + k0 + kk + lc);
        float4 wv = *(const float4*)(W + (size_t)(a0 + lr) * RNN_ + k0 + kk + lc);
        Hs[lr][lc] = hv.x; Hs[lr][lc + 1] = hv.y; Hs[lr][lc + 2] = hv.z; Hs[lr][lc + 3] = hv.w;
        Ws[lr][lc] = wv.x; Ws[lr][lc + 1] = wv.y; Ws[lr][lc + 2] = wv.z; Ws[lr][lc + 3] = wv.w;
        __syncthreads();
#pragma unroll
        for (int k = 0; k < 16; k++) {
            float hr[4], wr[4];
#pragma unroll
            for (int i = 0; i < 4; i++) hr[i] = Hs[ty * 4 + i][k];
#pragma unroll
            for (int j = 0; j < 4; j++) wr[j] = Ws[tx * 4 + j][k];
#pragma unroll
            for (int i = 0; i < 4; i++)
#pragma unroll
                for (int j = 0; j < 4; j++) c[i][j] += hr[i] * wr[j];
        }
        __syncthreads();
    }
#pragma unroll
    for (int i = 0; i < 4; i++)
#pragma unroll
        for (int j = 0; j < 4; j++)
            g_atth_part[blockIdx.z][(b0 + ty * 4 + i) * ATT_ + a0 + tx * 4 + j] = c[i][j];
}

// ------------------------------------------------------------------
// K2: dot[b,l] = sum_a tanh(f2[b,l,a] + att_h[b,a]) * w_alpha[a] + b_alpha
// Masked l (mask==0): entire 2KB row skipped; sentinel -1e30 written.
// Their dot never matters: weight = exp(dot-max)*mask and mask==0.
// ------------------------------------------------------------------
__global__ void k2_dot(const float* __restrict__ f2,
                       const float* __restrict__ mask,
                       const float* __restrict__ w_alpha,
                       const float* __restrict__ b_h2att,
                       const float* __restrict__ b_alpha) {
    __shared__ __align__(16) float atth[ATT_];
    __shared__ __align__(16) float wal[ATT_];
    const int b  = blockIdx.x;
    const int lc = blockIdx.y;
    const int tid = threadIdx.x;

    for (int i = tid; i < ATT_; i += 256) {
        float s = b_h2att[i];
#pragma unroll
        for (int p = 0; p < KSPLIT; p++) s += g_atth_part[p][b * ATT_ + i];
        atth[i] = s;
        wal[i] = w_alpha[i];
    }
    __syncthreads();

    const int warp = tid >> 5;
    const int lane = tid & 31;
    float4 ah[4], wa[4];
#pragma unroll
    for (int j = 0; j < 4; j++) {
        ah[j] = ((const float4*)atth)[lane + 32 * j];
        wa[j] = ((const float4*)wal)[lane + 32 * j];
    }
    const float balpha = *b_alpha;
    const int lbase = lc * (L_ / LSPLIT);
    const float* base = f2 + ((size_t)b * L_ + (size_t)lbase) * ATT_;
    const float* mrow = mask + (size_t)b * L_ + lbase;

    for (int li = warp; li < L_ / LSPLIT; li += 8) {
        if (mrow[li] == 0.f) {                   // uniform per warp
            if (lane == 0) g_dot[b * L_ + lbase + li] = -1e30f;
            continue;
        }
        const float4* row = (const float4*)(base + (size_t)li * ATT_);
        float s = 0.f;
#pragma unroll
        for (int j = 0; j < 4; j++) {
            float4 v = row[lane + 32 * j];
            s += tanh_fast(v.x + ah[j].x) * wa[j].x;
            s += tanh_fast(v.y + ah[j].y) * wa[j].y;
            s += tanh_fast(v.z + ah[j].z) * wa[j].z;
            s += tanh_fast(v.w + ah[j].w) * wa[j].w;
        }
#pragma unroll
        for (int o = 16; o; o >>= 1) s += __shfl_xor_sync(0xffffffffu, s, o);
        if (lane == 0) g_dot[b * L_ + lbase + li] = s + balpha;
    }
}

// ------------------------------------------------------------------
// K3: weight[b,l] = exp(dot-max)*mask / sum(exp(dot-max)*mask)
// (reference's inner softmax denominator cancels; any consistent max works,
//  sentinel -1e30 never wins the max since column 0 is always unmasked)
// ------------------------------------------------------------------
__global__ void k3_softmax(const float* __restrict__ mask) {
    const int b = blockIdx.x;
    const int tid = threadIdx.x;
    __shared__ float red[8];
    __shared__ float s_stat;

    float4 d = ((const float4*)(g_dot + b * L_))[tid];
    float4 m = ((const float4*)(mask + (size_t)b * L_))[tid];

    float mx = fmaxf(fmaxf(d.x, d.y), fmaxf(d.z, d.w));
#pragma unroll
    for (int o = 16; o; o >>= 1) mx = fmaxf(mx, __shfl_xor_sync(0xffffffffu, mx, o));
    if ((tid & 31) == 0) red[tid >> 5] = mx;
    __syncthreads();
    if (tid < 8) {
        float v = red[tid];
#pragma unroll
        for (int o = 4; o; o >>= 1) v = fmaxf(v, __shfl_xor_sync(0xffu, v, o));
        if (tid == 0) s_stat = v;
    }
    __syncthreads();
    const float bmax = s_stat;

    float4 e;
    e.x = __expf(d.x - bmax) * m.x;
    e.y = __expf(d.y - bmax) * m.y;
    e.z = __expf(d.z - bmax) * m.z;
    e.w = __expf(d.w - bmax) * m.w;
    float s = e.x + e.y + e.z + e.w;
#pragma unroll
    for (int o = 16; o; o >>= 1) s += __shfl_xor_sync(0xffffffffu, s, o);
    if ((tid & 31) == 0) red[tid >> 5] = s;
    __syncthreads();
    if (tid < 8) {
        float v = red[tid];
#pragma unroll
        for (int o = 4; o; o >>= 1) v += __shfl_xor_sync(0xffu, v, o);
        if (tid == 0) s_stat = v;
    }
    __syncthreads();
    const float inv = 1.0f / s_stat;
    float4 w4 = make_float4(e.x * inv, e.y * inv, e.z * inv, e.w * inv);
    ((float4*)(g_weight + b * L_))[tid] = w4;
}

// ------------------------------------------------------------------
// K4: partial[s][b,d] = sum_{l in split s, w[l]!=0} w[l] * f1[b,l,d]
// Deterministic ballot/popc compaction of nonzero weights -> dense loop,
// so ~50% of the f1 rows are never loaded but MLP stays dense.
// ------------------------------------------------------------------
__global__ void k4_weighted(const float* __restrict__ f1) {
    const int b = blockIdx.x;
    const int s = blockIdx.y;
    const int tid = threadIdx.x;
    __shared__ float wv[L_ / LSPLIT];
    __shared__ unsigned ball[4];
    __shared__ int idxs[L_ / LSPLIT];
    __shared__ float wcomp[L_ / LSPLIT];
    __shared__ int cnt_s;

    if (tid < L_ / LSPLIT) {
        float w = g_weight[b * L_ + s * (L_ / LSPLIT) + tid];
        wv[tid] = w;
        unsigned bm = __ballot_sync(0xffffffffu, w != 0.f);
        if ((tid & 31) == 0) ball[tid >> 5] = bm;
    }
    __syncthreads();
    if (tid < L_ / LSPLIT) {
        const int warp = tid >> 5;
        const int lane = tid & 31;
        int base = 0;
#pragma unroll
        for (int i = 0; i < 4; i++) if (i < warp) base += __popc(ball[i]);
        const unsigned bm = ball[warp];
        if (wv[tid] != 0.f) {
            int pos = base + __popc(bm & ((1u << lane) - 1u));
            idxs[pos] = tid;
            wcomp[pos] = wv[tid];
        }
        if (tid == (L_ / LSPLIT - 1)) cnt_s = base + __popc(bm);
    }
    __syncthreads();
    const int cnt = cnt_s;

    const float4* base4 = (const float4*)(f1 + ((size_t)b * L_ + (size_t)s * (L_ / LSPLIT)) * RNN_) + tid;
    float4 acc = make_float4(0.f, 0.f, 0.f, 0.f);
#pragma unroll 4
    for (int i = 0; i < cnt; i++) {
        const float w = wcomp[i];
        float4 v = base4[(size_t)idxs[i] * (RNN_ / 4)];
        acc.x += w * v.x;
        acc.y += w * v.y;
        acc.z += w * v.z;
        acc.w += w * v.w;
    }
    ((float4*)(g_part[s] + b * RNN_))[tid] = acc;
}

// ------------------------------------------------------------------
// K5: out[b,d] = sum_s partial[s][b,d]   (deterministic combine)
// ------------------------------------------------------------------
__global__ void k5_combine(float* __restrict__ out) {
    const int i = blockIdx.x * 256 + threadIdx.x;
    float4 a = make_float4(0.f, 0.f, 0.f, 0.f);
#pragma unroll
    for (int s = 0; s < LSPLIT; s++) {
        float4 v = ((const float4*)g_part)[(size_t)s * (B_ * RNN_ / 4) + i];
        a.x += v.x; a.y += v.y; a.z += v.z; a.w += v.w;
    }
    ((float4*)out)[i] = a;
}

extern "C" void kernel_launch(void* const* d_in, const int* in_sizes, int n_in,
                              void* d_out, int out_size) {
    const float* h    = (const float*)d_in[0];
    const float* f1   = (const float*)d_in[1];  // att_feats1 [128,1024,1024]
    const float* f2   = (const float*)d_in[2];  // att_feats2 [128,1024,512]
    const float* mask = (const float*)d_in[3];
    const float* W    = (const float*)d_in[4];  // [512,1024]
    const float* bh   = (const float*)d_in[5];  // [512]
    const float* wal  = (const float*)d_in[6];  // [512]
    const float* bal  = (const float*)d_in[7];  // scalar
    float* out = (float*)d_out;

    k1_gemm<<<dim3(ATT_ / 64, B_ / 64, KSPLIT), 256>>>(h, W);
    k2_dot<<<dim3(B_, LSPLIT), 256>>>(f2, mask, wal, bh, bal);
    k3_softmax<<<B_, 256>>>(mask);
    k4_weighted<<<dim3(B_, LSPLIT), 256>>>(f1);
    k5_combine<<<B_ * RNN_ / 1024, 256>>>(out);
}

// round 3
// speedup vs baseline: 1.5019x; 1.0044x over previous
#include <cuda_runtime.h>
#include <cuda_bf16.h>
#include <cstdint>

// Shapes
#define B_   128
#define L_   1024
#define RNN_ 1024
#define ATT_ 512
#define KSPLIT 8   // k-split for K1
#define NCHUNK 8   // chunks of the compacted list for K2/K4

// Scratch (device globals — allocation-free)
__device__ __align__(16) float g_atth_part[KSPLIT][B_ * ATT_];   // 2 MB
__device__ __align__(16) int   g_cidx[B_ * L_];                  // compacted l indices
__device__ int                 g_cnt[B_];                        // nonzero count per b
__device__ __align__(16) float g_cdot[B_ * L_];                  // dot at compacted pos
__device__ __align__(16) float g_cw[B_ * L_];                    // weight at compacted pos
__device__ __align__(16) float g_part[NCHUNK][B_ * RNN_];        // 4 MB partials

__device__ __forceinline__ float tanh_fast(float x) {
    float y;
    asm("tanh.approx.f32 %0, %1;" : "=f"(y) : "f"(x));
    return y;
}

// ------------------------------------------------------------------
// K0: order-preserving compaction of mask!=0 per batch row.
// 128 blocks x 256 threads (8 warps x 128 l each, iteration-major order)
// ------------------------------------------------------------------
__global__ void k0_compact(const float* __restrict__ mask) {
    const int b = blockIdx.x;
    const int tid = threadIdx.x;
    const int warp = tid >> 5;
    const int lane = tid & 31;
    __shared__ int wcnt[8], woff[8];
    const float* m = mask + (size_t)b * L_;

    unsigned bms[4];
    int cnt = 0;
#pragma unroll
    for (int it = 0; it < 4; it++) {
        const int l = warp * 128 + it * 32 + lane;
        bms[it] = __ballot_sync(0xffffffffu, m[l] != 0.f);
        cnt += __popc(bms[it]);
    }
    if (lane == 0) wcnt[warp] = cnt;
    __syncthreads();
    if (tid == 0) {
        int r = 0;
#pragma unroll
        for (int i = 0; i < 8; i++) { woff[i] = r; r += wcnt[i]; }
        g_cnt[b] = r;
    }
    __syncthreads();
    int off = woff[warp];
#pragma unroll
    for (int it = 0; it < 4; it++) {
        const int l = warp * 128 + it * 32 + lane;
        const unsigned bm = bms[it];
        if (bm & (1u << lane))
            g_cidx[b * L_ + off + __popc(bm & ((1u << lane) - 1u))] = l;
        off += __popc(bm);
    }
}

// ------------------------------------------------------------------
// K1: att_h partials = h[128,1024] @ W[512,1024]^T, 64x64 tiles, ksplit=8
// ------------------------------------------------------------------
__global__ void k1_gemm(const float* __restrict__ h, const float* __restrict__ W) {
    __shared__ float Hs[64][17];
    __shared__ float Ws[64][17];
    const int a0 = blockIdx.x * 64;
    const int b0 = blockIdx.y * 64;
    const int k0 = blockIdx.z * (RNN_ / KSPLIT);
    const int tid = threadIdx.x;
    const int tx = tid & 15;
    const int ty = tid >> 4;
    const int lr = tid >> 2;
    const int lc = (tid & 3) * 4;

    float c[4][4];
#pragma unroll
    for (int i = 0; i < 4; i++)
#pragma unroll
        for (int j = 0; j < 4; j++) c[i][j] = 0.f;

    for (int kk = 0; kk < RNN_ / KSPLIT; kk += 16) {
        float4 hv = *(const float4*)(h + (size_t)(b0 + lr) * RNN_ + k0 + kk + lc);
        float4 wv = *(const float4*)(W + (size_t)(a0 + lr) * RNN_ + k0 + kk + lc);
        Hs[lr][lc] = hv.x; Hs[lr][lc + 1] = hv.y; Hs[lr][lc + 2] = hv.z; Hs[lr][lc + 3] = hv.w;
        Ws[lr][lc] = wv.x; Ws[lr][lc + 1] = wv.y; Ws[lr][lc + 2] = wv.z; Ws[lr][lc + 3] = wv.w;
        __syncthreads();
#pragma unroll
        for (int k = 0; k < 16; k++) {
            float hr[4], wr[4];
#pragma unroll
            for (int i = 0; i < 4; i++) hr[i] = Hs[ty * 4 + i][k];
#pragma unroll
            for (int j = 0; j < 4; j++) wr[j] = Ws[tx * 4 + j][k];
#pragma unroll
            for (int i = 0; i < 4; i++)
#pragma unroll
                for (int j = 0; j < 4; j++) c[i][j] += hr[i] * wr[j];
        }
        __syncthreads();
    }
#pragma unroll
    for (int i = 0; i < 4; i++)
#pragma unroll
        for (int j = 0; j < 4; j++)
            g_atth_part[blockIdx.z][(b0 + ty * 4 + i) * ATT_ + a0 + tx * 4 + j] = c[i][j];
}

// ------------------------------------------------------------------
// K2: cdot[b,j] = sum_a tanh(f2[b,cidx[j],a] + att_h[b,a]) * w_alpha[a] + b_alpha
// over the COMPACTED index list, split into NCHUNK equal chunks -> balanced.
// att_h & w_alpha in registers; one warp per row.
// ------------------------------------------------------------------
__global__ void k2_dot(const float* __restrict__ f2,
                       const float* __restrict__ w_alpha,
                       const float* __restrict__ b_h2att,
                       const float* __restrict__ b_alpha) {
    __shared__ __align__(16) float atth[ATT_];
    __shared__ __align__(16) float wal[ATT_];
    const int b  = blockIdx.x;
    const int ch = blockIdx.y;
    const int tid = threadIdx.x;

    for (int i = tid; i < ATT_; i += 256) {
        float s = b_h2att[i];
#pragma unroll
        for (int p = 0; p < KSPLIT; p++) s += g_atth_part[p][b * ATT_ + i];
        atth[i] = s;
        wal[i] = w_alpha[i];
    }
    __syncthreads();

    const int warp = tid >> 5;
    const int lane = tid & 31;
    float4 ah[4], wa[4];
#pragma unroll
    for (int j = 0; j < 4; j++) {
        ah[j] = ((const float4*)atth)[lane + 32 * j];
        wa[j] = ((const float4*)wal)[lane + 32 * j];
    }
    const float balpha = *b_alpha;
    const int cnt = g_cnt[b];
    const int chunk = (cnt + NCHUNK - 1) / NCHUNK;
    const int start = ch * chunk;
    const int end = min(start + chunk, cnt);
    const float* fb = f2 + (size_t)b * L_ * ATT_;

    for (int j = start + warp; j < end; j += 8) {
        const int li = g_cidx[b * L_ + j];
        const float4* row = (const float4*)(fb + (size_t)li * ATT_);
        float s = 0.f;
#pragma unroll
        for (int q = 0; q < 4; q++) {
            float4 v = row[lane + 32 * q];
            s += tanh_fast(v.x + ah[q].x) * wa[q].x;
            s += tanh_fast(v.y + ah[q].y) * wa[q].y;
            s += tanh_fast(v.z + ah[q].z) * wa[q].z;
            s += tanh_fast(v.w + ah[q].w) * wa[q].w;
        }
#pragma unroll
        for (int o = 16; o; o >>= 1) s += __shfl_xor_sync(0xffffffffu, s, o);
        if (lane == 0) g_cdot[b * L_ + j] = s + balpha;
    }
}

// ------------------------------------------------------------------
// K3: softmax over the compacted dot vector (length cnt).
// weight[j] = exp(dot[j]-max) / sum(exp(dot-max))  (mask already applied
// by compaction; inner softmax denominator cancels algebraically)
// ------------------------------------------------------------------
__global__ void k3_softmax() {
    const int b = blockIdx.x;
    const int tid = threadIdx.x;
    const int cnt = g_cnt[b];
    __shared__ float red[8];
    __shared__ float s_stat;

    float vals[4];
    int nv = 0;
    for (int j = tid; j < cnt; j += 256) vals[nv++] = g_cdot[b * L_ + j];

    float mx = -1e30f;
    for (int i = 0; i < nv; i++) mx = fmaxf(mx, vals[i]);
#pragma unroll
    for (int o = 16; o; o >>= 1) mx = fmaxf(mx, __shfl_xor_sync(0xffffffffu, mx, o));
    if ((tid & 31) == 0) red[tid >> 5] = mx;
    __syncthreads();
    if (tid < 8) {
        float v = red[tid];
#pragma unroll
        for (int o = 4; o; o >>= 1) v = fmaxf(v, __shfl_xor_sync(0xffu, v, o));
        if (tid == 0) s_stat = v;
    }
    __syncthreads();
    const float bmax = s_stat;

    float e[4];
    float s = 0.f;
    for (int i = 0; i < nv; i++) { e[i] = __expf(vals[i] - bmax); s += e[i]; }
#pragma unroll
    for (int o = 16; o; o >>= 1) s += __shfl_xor_sync(0xffffffffu, s, o);
    if ((tid & 31) == 0) red[tid >> 5] = s;
    __syncthreads();
    if (tid < 8) {
        float v = red[tid];
#pragma unroll
        for (int o = 4; o; o >>= 1) v += __shfl_xor_sync(0xffu, v, o);
        if (tid == 0) s_stat = v;
    }
    __syncthreads();
    const float inv = 1.0f / s_stat;
    {
        int i = 0;
        for (int j = tid; j < cnt; j += 256) g_cw[b * L_ + j] = e[i++] * inv;
    }
}

// ------------------------------------------------------------------
// K4: partial[c][b,d] = sum_{j in chunk c} cw[j] * f1[b,cidx[j],d]
// Compacted + equal chunks -> near-perfect balance (cnt/8 ~ 64±2 rows).
// idx/w staged in smem; dense unrolled indexed stream.
// ------------------------------------------------------------------
__global__ void k4_weighted(const float* __restrict__ f1) {
    const int b = blockIdx.x;
    const int c = blockIdx.y;
    const int tid = threadIdx.x;
    __shared__ int   sidx[(L_ / NCHUNK) + NCHUNK];
    __shared__ float sw[(L_ / NCHUNK) + NCHUNK];

    const int cnt = g_cnt[b];
    const int chunk = (cnt + NCHUNK - 1) / NCHUNK;
    const int start = c * chunk;
    const int end = min(start + chunk, cnt);
    const int n = max(end - start, 0);

    for (int i = tid; i < n; i += 256) {
        sidx[i] = g_cidx[b * L_ + start + i];
        sw[i]   = g_cw[b * L_ + start + i];
    }
    __syncthreads();

    const float4* fb = (const float4*)(f1 + (size_t)b * L_ * RNN_) + tid;
    float4 acc = make_float4(0.f, 0.f, 0.f, 0.f);
#pragma unroll 8
    for (int i = 0; i < n; i++) {
        const float w = sw[i];
        float4 v = fb[(size_t)sidx[i] * (RNN_ / 4)];
        acc.x += w * v.x;
        acc.y += w * v.y;
        acc.z += w * v.z;
        acc.w += w * v.w;
    }
    ((float4*)(g_part[c] + b * RNN_))[tid] = acc;
}

// ------------------------------------------------------------------
// K5: out[b,d] = sum_c partial[c][b,d]   (deterministic combine)
// ------------------------------------------------------------------
__global__ void k5_combine(float* __restrict__ out) {
    const int i = blockIdx.x * 256 + threadIdx.x;
    float4 a = make_float4(0.f, 0.f, 0.f, 0.f);
#pragma unroll
    for (int c = 0; c < NCHUNK; c++) {
        float4 v = ((const float4*)g_part)[(size_t)c * (B_ * RNN_ / 4) + i];
        a.x += v.x; a.y += v.y; a.z += v.z; a.w += v.w;
    }
    ((float4*)out)[i] = a;
}

extern "C" void kernel_launch(void* const* d_in, const int* in_sizes, int n_in,
                              void* d_out, int out_size) {
    const float* h    = (const float*)d_in[0];
    const float* f1   = (const float*)d_in[1];  // att_feats1 [128,1024,1024]
    const float* f2   = (const float*)d_in[2];  // att_feats2 [128,1024,512]
    const float* mask = (const float*)d_in[3];
    const float* W    = (const float*)d_in[4];  // [512,1024]
    const float* bh   = (const float*)d_in[5];  // [512]
    const float* wal  = (const float*)d_in[6];  // [512]
    const float* bal  = (const float*)d_in[7];  // scalar
    float* out = (float*)d_out;

    k0_compact<<<B_, 256>>>(mask);
    k1_gemm<<<dim3(ATT_ / 64, B_ / 64, KSPLIT), 256>>>(h, W);
    k2_dot<<<dim3(B_, NCHUNK), 256>>>(f2, wal, bh, bal);
    k3_softmax<<<B_, 256>>>();
    k4_weighted<<<dim3(B_, NCHUNK), 256>>>(f1);
    k5_combine<<<B_ * RNN_ / 1024, 256>>>(out);
}

// round 4
// speedup vs baseline: 1.6606x; 1.1057x over previous
#include <cuda_runtime.h>
#include <cuda_bf16.h>
#include <cstdint>

// Shapes
#define B_   128
#define L_   1024
#define RNN_ 1024
#define ATT_ 512
#define KSPLIT 8   // k-split for K1
#define NCHUNK 8   // chunks of the compacted list for K2/K4

// Scratch (device globals — allocation-free)
__device__ __align__(16) float g_atth_part[KSPLIT][B_ * ATT_];   // 2 MB
__device__ __align__(16) float g_cdot[B_ * L_];                  // dot at compacted pos
__device__ __align__(16) float g_part[NCHUNK][B_ * RNN_];        // 4 MB partials

__device__ __forceinline__ float tanh_fast(float x) {
    float y;
    asm("tanh.approx.f32 %0, %1;" : "=f"(y) : "f"(x));
    return y;
}

// In-block order-preserving compaction of one mask row (1024 entries, 256 thr).
// Fills sidx[0..cnt) with ascending l where mask!=0; returns cnt.
__device__ __forceinline__ int compact_inblock(const float* __restrict__ m, int* sidx) {
    __shared__ int wcnt[8], woff[8];
    const int tid = threadIdx.x;
    const int warp = tid >> 5;
    const int lane = tid & 31;

    unsigned bms[4];
    int cnt = 0;
#pragma unroll
    for (int it = 0; it < 4; it++) {
        const int l = warp * 128 + it * 32 + lane;
        bms[it] = __ballot_sync(0xffffffffu, m[l] != 0.f);
        cnt += __popc(bms[it]);
    }
    if (lane == 0) wcnt[warp] = cnt;
    __syncthreads();
    if (tid == 0) {
        int r = 0;
#pragma unroll
        for (int i = 0; i < 8; i++) { woff[i] = r; r += wcnt[i]; }
        wcnt[0] = r;  // total (reuse slot; read after next barrier)
    }
    __syncthreads();
    int off = woff[warp];
#pragma unroll
    for (int it = 0; it < 4; it++) {
        const int l = warp * 128 + it * 32 + lane;
        const unsigned bm = bms[it];
        if (bm & (1u << lane))
            sidx[off + __popc(bm & ((1u << lane) - 1u))] = l;
        off += __popc(bm);
    }
    const int total = wcnt[0];
    __syncthreads();
    return total;
}

// ------------------------------------------------------------------
// K1: att_h partials = h[128,1024] @ W[512,1024]^T, 64x64 tiles, ksplit=8
// ------------------------------------------------------------------
__global__ void k1_gemm(const float* __restrict__ h, const float* __restrict__ W) {
    __shared__ float Hs[64][17];
    __shared__ float Ws[64][17];
    const int a0 = blockIdx.x * 64;
    const int b0 = blockIdx.y * 64;
    const int k0 = blockIdx.z * (RNN_ / KSPLIT);
    const int tid = threadIdx.x;
    const int tx = tid & 15;
    const int ty = tid >> 4;
    const int lr = tid >> 2;
    const int lc = (tid & 3) * 4;

    float c[4][4];
#pragma unroll
    for (int i = 0; i < 4; i++)
#pragma unroll
        for (int j = 0; j < 4; j++) c[i][j] = 0.f;

    for (int kk = 0; kk < RNN_ / KSPLIT; kk += 16) {
        float4 hv = *(const float4*)(h + (size_t)(b0 + lr) * RNN_ + k0 + kk + lc);
        float4 wv = *(const float4*)(W + (size_t)(a0 + lr) * RNN_ + k0 + kk + lc);
        Hs[lr][lc] = hv.x; Hs[lr][lc + 1] = hv.y; Hs[lr][lc + 2] = hv.z; Hs[lr][lc + 3] = hv.w;
        Ws[lr][lc] = wv.x; Ws[lr][lc + 1] = wv.y; Ws[lr][lc + 2] = wv.z; Ws[lr][lc + 3] = wv.w;
        __syncthreads();
#pragma unroll
        for (int k = 0; k < 16; k++) {
            float hr[4], wr[4];
#pragma unroll
            for (int i = 0; i < 4; i++) hr[i] = Hs[ty * 4 + i][k];
#pragma unroll
            for (int j = 0; j < 4; j++) wr[j] = Ws[tx * 4 + j][k];
#pragma unroll
            for (int i = 0; i < 4; i++)
#pragma unroll
                for (int j = 0; j < 4; j++) c[i][j] += hr[i] * wr[j];
        }
        __syncthreads();
    }
#pragma unroll
    for (int i = 0; i < 4; i++)
#pragma unroll
        for (int j = 0; j < 4; j++)
            g_atth_part[blockIdx.z][(b0 + ty * 4 + i) * ATT_ + a0 + tx * 4 + j] = c[i][j];
}

// ------------------------------------------------------------------
// K2: cdot[b,j] = sum_a tanh(f2[b,cidx[j],a] + att_h[b,a]) * w_alpha[a] + b_alpha
// Compaction recomputed in-block (mask row is L2-hot). MUFU-bound.
// ------------------------------------------------------------------
__global__ void k2_dot(const float* __restrict__ f2,
                       const float* __restrict__ mask,
                       const float* __restrict__ w_alpha,
                       const float* __restrict__ b_h2att,
                       const float* __restrict__ b_alpha) {
    __shared__ __align__(16) float atth[ATT_];
    __shared__ __align__(16) float wal[ATT_];
    __shared__ int sidx[L_];
    const int b  = blockIdx.x;
    const int ch = blockIdx.y;
    const int tid = threadIdx.x;

    const int cnt = compact_inblock(mask + (size_t)b * L_, sidx);

    for (int i = tid; i < ATT_; i += 256) {
        float s = b_h2att[i];
#pragma unroll
        for (int p = 0; p < KSPLIT; p++) s += g_atth_part[p][b * ATT_ + i];
        atth[i] = s;
        wal[i] = w_alpha[i];
    }
    __syncthreads();

    const int warp = tid >> 5;
    const int lane = tid & 31;
    float4 ah[4], wa[4];
#pragma unroll
    for (int j = 0; j < 4; j++) {
        ah[j] = ((const float4*)atth)[lane + 32 * j];
        wa[j] = ((const float4*)wal)[lane + 32 * j];
    }
    const float balpha = *b_alpha;
    const int chunk = (cnt + NCHUNK - 1) / NCHUNK;
    const int start = ch * chunk;
    const int end = min(start + chunk, cnt);
    const float* fb = f2 + (size_t)b * L_ * ATT_;

    for (int j = start + warp; j < end; j += 8) {
        const int li = sidx[j];
        const float4* row = (const float4*)(fb + (size_t)li * ATT_);
        float s = 0.f;
#pragma unroll
        for (int q = 0; q < 4; q++) {
            float4 v = row[lane + 32 * q];
            s += tanh_fast(v.x + ah[q].x) * wa[q].x;
            s += tanh_fast(v.y + ah[q].y) * wa[q].y;
            s += tanh_fast(v.z + ah[q].z) * wa[q].z;
            s += tanh_fast(v.w + ah[q].w) * wa[q].w;
        }
#pragma unroll
        for (int o = 16; o; o >>= 1) s += __shfl_xor_sync(0xffffffffu, s, o);
        if (lane == 0) g_cdot[b * L_ + j] = s + balpha;
    }
}

// ------------------------------------------------------------------
// K4: softmax normalization fused in prologue + weighted gather.
// partial[c][b,d] = sum_{j in chunk c} w[j] * f1[b,cidx[j],d]
// w[j] = exp(cdot[j]-max)/sum(exp(cdot-max))  (mask applied by compaction;
// reference's inner softmax denominator cancels algebraically)
// ------------------------------------------------------------------
__global__ void k4_weighted(const float* __restrict__ f1,
                            const float* __restrict__ mask) {
    __shared__ int sidx[L_];
    __shared__ float sw[(L_ / NCHUNK) + NCHUNK];
    __shared__ float red[8];
    __shared__ float stat;
    const int b = blockIdx.x;
    const int c = blockIdx.y;
    const int tid = threadIdx.x;
    const int warp = tid >> 5;
    const int lane = tid & 31;

    const int cnt = compact_inblock(mask + (size_t)b * L_, sidx);

    // --- block softmax stats over g_cdot[b, 0..cnt) ---
    float mx = -1e30f;
    for (int j = tid; j < cnt; j += 256) mx = fmaxf(mx, g_cdot[b * L_ + j]);
#pragma unroll
    for (int o = 16; o; o >>= 1) mx = fmaxf(mx, __shfl_xor_sync(0xffffffffu, mx, o));
    if (lane == 0) red[warp] = mx;
    __syncthreads();
    if (tid < 8) {
        float v = red[tid];
#pragma unroll
        for (int o = 4; o; o >>= 1) v = fmaxf(v, __shfl_xor_sync(0xffu, v, o));
        if (tid == 0) stat = v;
    }
    __syncthreads();
    const float bmax = stat;

    float s = 0.f;
    for (int j = tid; j < cnt; j += 256) s += __expf(g_cdot[b * L_ + j] - bmax);
#pragma unroll
    for (int o = 16; o; o >>= 1) s += __shfl_xor_sync(0xffffffffu, s, o);
    __syncthreads();            // red[] reuse hazard
    if (lane == 0) red[warp] = s;
    __syncthreads();
    if (tid < 8) {
        float v = red[tid];
#pragma unroll
        for (int o = 4; o; o >>= 1) v += __shfl_xor_sync(0xffu, v, o);
        if (tid == 0) stat = v;
    }
    __syncthreads();
    const float inv = 1.0f / stat;

    // --- own chunk weights ---
    const int chunk = (cnt + NCHUNK - 1) / NCHUNK;
    const int start = c * chunk;
    const int end = min(start + chunk, cnt);
    const int n = max(end - start, 0);
    for (int i = tid; i < n; i += 256)
        sw[i] = __expf(g_cdot[b * L_ + start + i] - bmax) * inv;
    __syncthreads();

    // --- gather-accumulate ---
    const float4* fb = (const float4*)(f1 + (size_t)b * L_ * RNN_) + tid;
    float4 acc = make_float4(0.f, 0.f, 0.f, 0.f);
#pragma unroll 8
    for (int i = 0; i < n; i++) {
        const float w = sw[i];
        float4 v = fb[(size_t)sidx[start + i] * (RNN_ / 4)];
        acc.x += w * v.x;
        acc.y += w * v.y;
        acc.z += w * v.z;
        acc.w += w * v.w;
    }
    ((float4*)(g_part[c] + b * RNN_))[tid] = acc;
}

// ------------------------------------------------------------------
// K5: out[b,d] = sum_c partial[c][b,d]   (deterministic combine)
// ------------------------------------------------------------------
__global__ void k5_combine(float* __restrict__ out) {
    const int i = blockIdx.x * 256 + threadIdx.x;
    float4 a = make_float4(0.f, 0.f, 0.f, 0.f);
#pragma unroll
    for (int c = 0; c < NCHUNK; c++) {
        float4 v = ((const float4*)g_part)[(size_t)c * (B_ * RNN_ / 4) + i];
        a.x += v.x; a.y += v.y; a.z += v.z; a.w += v.w;
    }
    ((float4*)out)[i] = a;
}

extern "C" void kernel_launch(void* const* d_in, const int* in_sizes, int n_in,
                              void* d_out, int out_size) {
    const float* h    = (const float*)d_in[0];
    const float* f1   = (const float*)d_in[1];  // att_feats1 [128,1024,1024]
    const float* f2   = (const float*)d_in[2];  // att_feats2 [128,1024,512]
    const float* mask = (const float*)d_in[3];
    const float* W    = (const float*)d_in[4];  // [512,1024]
    const float* bh   = (const float*)d_in[5];  // [512]
    const float* wal  = (const float*)d_in[6];  // [512]
    const float* bal  = (const float*)d_in[7];  // scalar
    float* out = (float*)d_out;

    k1_gemm<<<dim3(ATT_ / 64, B_ / 64, KSPLIT), 256>>>(h, W);
    k2_dot<<<dim3(B_, NCHUNK), 256>>>(f2, mask, wal, bh, bal);
    k4_weighted<<<dim3(B_, NCHUNK), 256>>>(f1, mask);
    k5_combine<<<B_ * RNN_ / 1024, 256>>>(out);
}